// round 6
// baseline (speedup 1.0000x reference)
#include <cuda_runtime.h>
#include <cuda_bf16.h>

#define BB 64
#define TT 512
#define CC 384
#define HH 64
#define BT (BB*TT)

// Scratch for projected Q,K,V (single static device array -- no allocation).
__device__ float g_scratch[3 * BT * HH];
#define g_Q (g_scratch)
#define g_K (g_scratch + BT*HH)
#define g_V (g_scratch + 2*BT*HH)

// ---------------------------------------------------------------------------
// Projection GEMM: Out[BT x 64] = x[BT x 384] @ W[384 x 64], for Wq/Wk/Wv.
// grid (BT/64, 3), block 256. BM=64, BN=64, BK=32, 4x4 register tile/thread.
// ---------------------------------------------------------------------------
__global__ void proj_kernel(const float* __restrict__ x,
                            const float* __restrict__ Wq,
                            const float* __restrict__ Wk,
                            const float* __restrict__ Wv) {
    const int m0 = blockIdx.x * 64;
    const float* W = (blockIdx.y == 0) ? Wq : (blockIdx.y == 1 ? Wk : Wv);
    float* Out = g_scratch + (size_t)blockIdx.y * BT * HH;

    __shared__ float As[32][65];   // [k][m], stride 65 -> conflict-free transpose store
    __shared__ float Bs[32][68];   // [k][n]

    const int tid = threadIdx.x;
    const int ty  = tid / 16;      // 16 row groups of 4
    const int tx  = tid % 16;      // 16 col groups of 4

    float acc[4][4] = {};

    for (int k0 = 0; k0 < CC; k0 += 32) {
        // Load A tile 64x32 (coalesced along C)
        #pragma unroll
        for (int i = 0; i < 8; i++) {
            int idx = tid + i * 256;          // 0..2047
            int m = idx >> 5;
            int k = idx & 31;
            As[k][m] = x[(size_t)(m0 + m) * CC + k0 + k];
        }
        // Load W tile 32x64 (coalesced along H)
        #pragma unroll
        for (int i = 0; i < 8; i++) {
            int idx = tid + i * 256;
            int k = idx >> 6;
            int n = idx & 63;
            Bs[k][n] = W[(size_t)(k0 + k) * HH + n];
        }
        __syncthreads();

        #pragma unroll
        for (int k = 0; k < 32; k++) {
            float a[4], b[4];
            #pragma unroll
            for (int i = 0; i < 4; i++) a[i] = As[k][ty * 4 + i];
            #pragma unroll
            for (int j = 0; j < 4; j++) b[j] = Bs[k][tx * 4 + j];
            #pragma unroll
            for (int i = 0; i < 4; i++)
                #pragma unroll
                for (int j = 0; j < 4; j++)
                    acc[i][j] += a[i] * b[j];
        }
        __syncthreads();
    }

    #pragma unroll
    for (int i = 0; i < 4; i++)
        #pragma unroll
        for (int j = 0; j < 4; j++)
            Out[(size_t)(m0 + ty * 4 + i) * HH + tx * 4 + j] = acc[i][j];
}

// ---------------------------------------------------------------------------
// Flash attention: one thread per query row, online softmax.
// grid (T/QT, B), block QT=128 threads. KV tiles of KT=32 rows in smem.
// ---------------------------------------------------------------------------
#define QT 128
#define KT 32

__global__ __launch_bounds__(QT, 2)
void attn_kernel(float* __restrict__ out) {
    const int b   = blockIdx.y;
    const int q0  = blockIdx.x * QT;
    const int tid = threadIdx.x;
    const int qi  = q0 + tid;

    __shared__ float Ks[KT][HH];        // broadcast reads -> no pad needed
    __shared__ float Vs[KT][HH];
    __shared__ float sS[QT][KT + 1];    // per-thread score row, conflict-free

    // Load Q row into registers (vectorized)
    const float4* Qg = (const float4*)(g_Q + (size_t)(b * TT + qi) * HH);
    float qv[HH];
    #pragma unroll
    for (int h4 = 0; h4 < HH / 4; h4++) {
        float4 t = Qg[h4];
        qv[h4 * 4 + 0] = t.x; qv[h4 * 4 + 1] = t.y;
        qv[h4 * 4 + 2] = t.z; qv[h4 * 4 + 3] = t.w;
    }

    float acc[HH];
    #pragma unroll
    for (int h = 0; h < HH; h++) acc[h] = 0.f;
    float m = -1e30f, l = 0.f;
    const float scale = 0.125f;   // 1/sqrt(64)

    const int ntiles = (q0 + QT - 1) / KT + 1;   // causal: tiles past block diag skipped
    for (int jt = 0; jt < ntiles; jt++) {
        const int k0 = jt * KT;

        __syncthreads();
        {   // cooperative tile load: KT*HH/4 = 512 float4, 128 threads -> 4 each
            const float4* Kg = (const float4*)(g_K + (size_t)(b * TT + k0) * HH);
            const float4* Vg = (const float4*)(g_V + (size_t)(b * TT + k0) * HH);
            float4* Ks4 = (float4*)&Ks[0][0];
            float4* Vs4 = (float4*)&Vs[0][0];
            #pragma unroll
            for (int i = 0; i < (KT * HH / 4) / QT; i++) {
                Ks4[tid + i * QT] = Kg[tid + i * QT];
                Vs4[tid + i * QT] = Vg[tid + i * QT];
            }
        }
        __syncthreads();

        // Scores for this tile
        float tmax = m;
        for (int j = 0; j < KT; j++) {
            float d = 0.f;
            #pragma unroll
            for (int h = 0; h < HH; h++) d += qv[h] * Ks[j][h];
            d *= scale;
            d = (k0 + j > qi) ? -1e30f : d;
            sS[tid][j] = d;
            tmax = fmaxf(tmax, d);
        }

        // Online softmax rescale
        float alpha = __expf(m - tmax);
        m = tmax;
        l *= alpha;
        #pragma unroll
        for (int h = 0; h < HH; h++) acc[h] *= alpha;

        // P @ V
        for (int j = 0; j < KT; j++) {
            const float p = __expf(sS[tid][j] - m);
            l += p;
            #pragma unroll
            for (int h = 0; h < HH; h++) acc[h] += p * Vs[j][h];
        }
    }

    const float inv = 1.f / l;
    float4* Og = (float4*)(out + (size_t)(b * TT + qi) * HH);
    #pragma unroll
    for (int h4 = 0; h4 < HH / 4; h4++) {
        float4 t;
        t.x = acc[h4 * 4 + 0] * inv;
        t.y = acc[h4 * 4 + 1] * inv;
        t.z = acc[h4 * 4 + 2] * inv;
        t.w = acc[h4 * 4 + 3] * inv;
        Og[h4] = t;
    }
}

// ---------------------------------------------------------------------------
extern "C" void kernel_launch(void* const* d_in, const int* in_sizes, int n_in,
                              void* d_out, int out_size) {
    const float* x  = (const float*)d_in[0];
    const float* Wq = (const float*)d_in[1];
    const float* Wk = (const float*)d_in[2];
    const float* Wv = (const float*)d_in[3];
    float* out = (float*)d_out;

    proj_kernel<<<dim3(BT / 64, 3), 256>>>(x, Wq, Wk, Wv);
    attn_kernel<<<dim3(TT / QT, BB), QT>>>(out);
}

// round 7
// speedup vs baseline: 1.4428x; 1.4428x over previous
#include <cuda_runtime.h>
#include <cuda_bf16.h>
#include <cstdint>

#define BB 64
#define TT 512
#define CC 384
#define HH 64
#define BT (BB*TT)

// Scratch for projected Q,K,V (single static device array -- no allocation).
__device__ float g_scratch[3 * BT * HH];
#define g_Q (g_scratch)
#define g_K (g_scratch + BT*HH)
#define g_V (g_scratch + 2*BT*HH)

// ---------------------------------------------------------------------------
// Helpers: TF32 convert + m16n8k8 TF32 MMA
// ---------------------------------------------------------------------------
__device__ __forceinline__ float to_tf32(float x) {
    float r;
    asm("cvt.rna.tf32.f32 %0, %1;" : "=f"(r) : "f"(x));
    return r;
}

__device__ __forceinline__ void mma_tf32(float* c, const uint32_t* a, const uint32_t* b) {
    asm volatile(
        "mma.sync.aligned.m16n8k8.row.col.f32.tf32.tf32.f32 "
        "{%0,%1,%2,%3}, {%4,%5,%6,%7}, {%8,%9}, {%0,%1,%2,%3};"
        : "+f"(c[0]), "+f"(c[1]), "+f"(c[2]), "+f"(c[3])
        : "r"(a[0]), "r"(a[1]), "r"(a[2]), "r"(a[3]),
          "r"(b[0]), "r"(b[1]));
}

// ---------------------------------------------------------------------------
// Projection GEMM (TF32 tensor): Out[BT x 64] = x[BT x 384] @ W[384 x 64].
// grid (BT/128, 3), block 256 (8 warps). BM=128, BN=64, BK=32.
// Warp grid 4x2 (wm 0..3 covers 32 M-rows each, wn 0..1 covers 32 N-cols).
// Per warp: 2 m-tiles (16) x 4 n-tiles (8), k-steps of 8.
// ---------------------------------------------------------------------------
__global__ __launch_bounds__(256, 2)
void proj_mma(const float* __restrict__ x,
              const float* __restrict__ Wq,
              const float* __restrict__ Wk,
              const float* __restrict__ Wv) {
    const int m0 = blockIdx.x * 128;
    const float* W = (blockIdx.y == 0) ? Wq : (blockIdx.y == 1 ? Wk : Wv);
    float* Out = g_scratch + (size_t)blockIdx.y * BT * HH;

    __shared__ float Xs[128][36];   // [m][k], pad 36 -> 2-way worst on frag reads
    __shared__ float Ws[32][68];    // [k][n]

    const int tid  = threadIdx.x;
    const int lane = tid & 31;
    const int warp = tid >> 5;
    const int wm   = warp >> 1;     // 0..3
    const int wn   = warp & 1;      // 0..1
    const int g    = lane >> 2;     // group id 0..7
    const int t    = lane & 3;      // thread in group 0..3

    const uint32_t* Xs32 = (const uint32_t*)&Xs[0][0];
    const uint32_t* Ws32 = (const uint32_t*)&Ws[0][0];

    float acc[2][4][4];
    #pragma unroll
    for (int mt = 0; mt < 2; mt++)
        #pragma unroll
        for (int nt = 0; nt < 4; nt++)
            #pragma unroll
            for (int r = 0; r < 4; r++) acc[mt][nt][r] = 0.f;

    for (int k0 = 0; k0 < CC; k0 += 32) {
        // Load X tile 128x32 (coalesced float4), cvt to tf32
        #pragma unroll
        for (int i = 0; i < 4; i++) {
            int idx4 = tid + i * 256;         // 0..1023
            int m  = idx4 >> 3;
            int c4 = idx4 & 7;
            float4 v = *(const float4*)(x + (size_t)(m0 + m) * CC + k0 + c4 * 4);
            Xs[m][c4 * 4 + 0] = to_tf32(v.x);
            Xs[m][c4 * 4 + 1] = to_tf32(v.y);
            Xs[m][c4 * 4 + 2] = to_tf32(v.z);
            Xs[m][c4 * 4 + 3] = to_tf32(v.w);
        }
        // Load W tile 32x64, cvt to tf32
        #pragma unroll
        for (int i = 0; i < 2; i++) {
            int idx4 = tid + i * 256;         // 0..511
            int k  = idx4 >> 4;
            int n4 = idx4 & 15;
            float4 v = *(const float4*)(W + (size_t)(k0 + k) * HH + n4 * 4);
            Ws[k][n4 * 4 + 0] = to_tf32(v.x);
            Ws[k][n4 * 4 + 1] = to_tf32(v.y);
            Ws[k][n4 * 4 + 2] = to_tf32(v.z);
            Ws[k][n4 * 4 + 3] = to_tf32(v.w);
        }
        __syncthreads();

        #pragma unroll
        for (int ks = 0; ks < 4; ks++) {
            const int kk = ks * 8;
            uint32_t a[2][4], bfr[4][2];
            #pragma unroll
            for (int mt = 0; mt < 2; mt++) {
                int r = wm * 32 + mt * 16 + g;
                int c = kk + t;
                a[mt][0] = Xs32[(r)     * 36 + c];
                a[mt][1] = Xs32[(r + 8) * 36 + c];
                a[mt][2] = Xs32[(r)     * 36 + c + 4];
                a[mt][3] = Xs32[(r + 8) * 36 + c + 4];
            }
            #pragma unroll
            for (int nt = 0; nt < 4; nt++) {
                int n = wn * 32 + nt * 8 + g;
                bfr[nt][0] = Ws32[(kk + t)     * 68 + n];
                bfr[nt][1] = Ws32[(kk + t + 4) * 68 + n];
            }
            #pragma unroll
            for (int mt = 0; mt < 2; mt++)
                #pragma unroll
                for (int nt = 0; nt < 4; nt++)
                    mma_tf32(acc[mt][nt], a[mt], bfr[nt]);
        }
        __syncthreads();
    }

    // Epilogue: C frag (r=g / g+8, cols 2t, 2t+1)
    #pragma unroll
    for (int mt = 0; mt < 2; mt++) {
        int r0 = m0 + wm * 32 + mt * 16 + g;
        #pragma unroll
        for (int nt = 0; nt < 4; nt++) {
            int cb = wn * 32 + nt * 8 + 2 * t;
            float2 lo = make_float2(acc[mt][nt][0], acc[mt][nt][1]);
            float2 hi = make_float2(acc[mt][nt][2], acc[mt][nt][3]);
            *(float2*)(Out + (size_t)(r0)     * HH + cb) = lo;
            *(float2*)(Out + (size_t)(r0 + 8) * HH + cb) = hi;
        }
    }
}

// ---------------------------------------------------------------------------
// Flash attention, block-GEMM form (fp32).
// Block = 64 query rows x one batch; KV tiles of 32 rows.
// 256 threads as 16(ty: 4 q-rows each) x 16(tx).
// GEMM1: S[64x32], thread tile 4x2.  GEMM2: O[64x64], thread tile 4x4.
// Online softmax in registers; row stats via 16-lane shfl.bfly.
// ---------------------------------------------------------------------------
__global__ __launch_bounds__(256, 3)
void attn2(float* __restrict__ out) {
    const int b  = blockIdx.y;
    const int qb = blockIdx.x;
    const int q0 = qb * 64;
    const int tid = threadIdx.x;
    const int ty = tid >> 4;      // 0..15 -> q rows ty*4..+3
    const int tx = tid & 15;

    __shared__ float Qt[64][68];  // [h][q], scaled
    __shared__ float Kt[64][36];  // [h][k]
    __shared__ float Vs[32][68];  // [k][n]
    __shared__ float Pt[32][65];  // [k][q]

    // Load Q transposed + pre-scaled (1/sqrt(64) = 0.125)
    {
        int q  = tid & 63;
        int h0 = (tid >> 6) * 16;
        const float* src = g_Q + (size_t)(b * TT + q0 + q) * HH + h0;
        #pragma unroll
        for (int j = 0; j < 16; j++) Qt[h0 + j][q] = src[j] * 0.125f;
    }

    float o[4][4];
    float mrow[4], lrow[4];
    #pragma unroll
    for (int i = 0; i < 4; i++) {
        mrow[i] = -1e30f; lrow[i] = 0.f;
        #pragma unroll
        for (int j = 0; j < 4; j++) o[i][j] = 0.f;
    }

    const int ntiles = 2 * qb + 2;
    for (int jt = 0; jt < ntiles; jt++) {
        const int k0 = jt * 32;

        __syncthreads();   // protect Kt/Vs/Pt from previous iteration readers
        // Load K tile transposed: Kt[h][k]
        {
            int k  = tid & 31;
            int h0 = (tid >> 5) * 8;
            const float* src = g_K + (size_t)(b * TT + k0 + k) * HH + h0;
            #pragma unroll
            for (int j = 0; j < 8; j++) Kt[h0 + j][k] = src[j];
        }
        // Load V tile natural: Vs[k][n]
        #pragma unroll
        for (int i = 0; i < 2; i++) {
            int e  = tid + i * 256;
            int k  = e >> 4;
            int n4 = e & 15;
            float4 v = *(const float4*)(g_V + (size_t)(b * TT + k0 + k) * HH + n4 * 4);
            *(float4*)&Vs[k][n4 * 4] = v;
        }
        __syncthreads();

        // GEMM1: S = Q @ K^T  (4x2 per thread)
        float s[4][2] = {};
        #pragma unroll 8
        for (int h = 0; h < 64; h++) {
            float4 qa = *(const float4*)&Qt[h][ty * 4];
            float2 kb = *(const float2*)&Kt[h][tx * 2];
            s[0][0] += qa.x * kb.x;  s[0][1] += qa.x * kb.y;
            s[1][0] += qa.y * kb.x;  s[1][1] += qa.y * kb.y;
            s[2][0] += qa.z * kb.x;  s[2][1] += qa.z * kb.y;
            s[3][0] += qa.w * kb.x;  s[3][1] += qa.w * kb.y;
        }

        // Causal mask (only the last two tiles touch the diagonal band)
        if (jt >= 2 * qb) {
            #pragma unroll
            for (int i = 0; i < 4; i++)
                #pragma unroll
                for (int j = 0; j < 2; j++) {
                    int q = q0 + ty * 4 + i;
                    int k = k0 + tx * 2 + j;
                    if (k > q) s[i][j] = -1e30f;
                }
        }

        // Online softmax (registers + 16-lane bfly reductions)
        #pragma unroll
        for (int i = 0; i < 4; i++) {
            float tm = fmaxf(s[i][0], s[i][1]);
            tm = fmaxf(tm, __shfl_xor_sync(0xffffffffu, tm, 1));
            tm = fmaxf(tm, __shfl_xor_sync(0xffffffffu, tm, 2));
            tm = fmaxf(tm, __shfl_xor_sync(0xffffffffu, tm, 4));
            tm = fmaxf(tm, __shfl_xor_sync(0xffffffffu, tm, 8));
            float nm    = fmaxf(mrow[i], tm);
            float alpha = __expf(mrow[i] - nm);
            mrow[i] = nm;
            float p0 = __expf(s[i][0] - nm);
            float p1 = __expf(s[i][1] - nm);
            Pt[tx * 2 + 0][ty * 4 + i] = p0;
            Pt[tx * 2 + 1][ty * 4 + i] = p1;
            float ts = p0 + p1;
            ts += __shfl_xor_sync(0xffffffffu, ts, 1);
            ts += __shfl_xor_sync(0xffffffffu, ts, 2);
            ts += __shfl_xor_sync(0xffffffffu, ts, 4);
            ts += __shfl_xor_sync(0xffffffffu, ts, 8);
            lrow[i] = lrow[i] * alpha + ts;
            o[i][0] *= alpha; o[i][1] *= alpha; o[i][2] *= alpha; o[i][3] *= alpha;
        }
        __syncthreads();   // Pt ready for all threads

        // GEMM2: O += P @ V  (4x4 per thread)
        #pragma unroll 4
        for (int k = 0; k < 32; k++) {
            float4 vb = *(const float4*)&Vs[k][tx * 4];
            #pragma unroll
            for (int i = 0; i < 4; i++) {
                float p = Pt[k][ty * 4 + i];
                o[i][0] += p * vb.x;
                o[i][1] += p * vb.y;
                o[i][2] += p * vb.z;
                o[i][3] += p * vb.w;
            }
        }
    }

    // Normalize and store
    #pragma unroll
    for (int i = 0; i < 4; i++) {
        float inv = 1.f / lrow[i];
        float4 r = make_float4(o[i][0] * inv, o[i][1] * inv,
                               o[i][2] * inv, o[i][3] * inv);
        *(float4*)(out + (size_t)(b * TT + q0 + ty * 4 + i) * HH + tx * 4) = r;
    }
}

// ---------------------------------------------------------------------------
extern "C" void kernel_launch(void* const* d_in, const int* in_sizes, int n_in,
                              void* d_out, int out_size) {
    const float* x  = (const float*)d_in[0];
    const float* Wq = (const float*)d_in[1];
    const float* Wk = (const float*)d_in[2];
    const float* Wv = (const float*)d_in[3];
    float* out = (float*)d_out;

    proj_mma<<<dim3(BT / 128, 3), 256>>>(x, Wq, Wk, Wv);
    attn2<<<dim3(TT / 64, BB), 256>>>(out);
}

// round 8
// speedup vs baseline: 2.7087x; 1.8774x over previous
#include <cuda_runtime.h>
#include <cuda_bf16.h>
#include <cstdint>

#define BB 64
#define TT 512
#define CC 384
#define HH 64
#define BT (BB*TT)

// Scratch for projected Q,K,V (single static device array -- no allocation).
__device__ float g_scratch[3 * BT * HH];
#define g_Q (g_scratch)
#define g_K (g_scratch + BT*HH)
#define g_V (g_scratch + 2*BT*HH)

// ---------------------------------------------------------------------------
// Helpers: TF32 convert + m16n8k8 TF32 MMA
// ---------------------------------------------------------------------------
__device__ __forceinline__ float to_tf32(float x) {
    float r;
    asm("cvt.rna.tf32.f32 %0, %1;" : "=f"(r) : "f"(x));
    return r;
}

__device__ __forceinline__ void mma_tf32(float* c, const uint32_t* a, const uint32_t* b) {
    asm volatile(
        "mma.sync.aligned.m16n8k8.row.col.f32.tf32.tf32.f32 "
        "{%0,%1,%2,%3}, {%4,%5,%6,%7}, {%8,%9}, {%0,%1,%2,%3};"
        : "+f"(c[0]), "+f"(c[1]), "+f"(c[2]), "+f"(c[3])
        : "r"(a[0]), "r"(a[1]), "r"(a[2]), "r"(a[3]),
          "r"(b[0]), "r"(b[1]));
}

// ---------------------------------------------------------------------------
// Projection GEMM (TF32 tensor): Out[BT x 64] = x[BT x 384] @ W[384 x 64].
// (unchanged from R7 -- measured ~64us)
// ---------------------------------------------------------------------------
__global__ __launch_bounds__(256, 2)
void proj_mma(const float* __restrict__ x,
              const float* __restrict__ Wq,
              const float* __restrict__ Wk,
              const float* __restrict__ Wv) {
    const int m0 = blockIdx.x * 128;
    const float* W = (blockIdx.y == 0) ? Wq : (blockIdx.y == 1 ? Wk : Wv);
    float* Out = g_scratch + (size_t)blockIdx.y * BT * HH;

    __shared__ float Xs[128][36];
    __shared__ float Ws[32][68];

    const int tid  = threadIdx.x;
    const int lane = tid & 31;
    const int warp = tid >> 5;
    const int wm   = warp >> 1;
    const int wn   = warp & 1;
    const int g    = lane >> 2;
    const int t    = lane & 3;

    const uint32_t* Xs32 = (const uint32_t*)&Xs[0][0];
    const uint32_t* Ws32 = (const uint32_t*)&Ws[0][0];

    float acc[2][4][4];
    #pragma unroll
    for (int mt = 0; mt < 2; mt++)
        #pragma unroll
        for (int nt = 0; nt < 4; nt++)
            #pragma unroll
            for (int r = 0; r < 4; r++) acc[mt][nt][r] = 0.f;

    for (int k0 = 0; k0 < CC; k0 += 32) {
        #pragma unroll
        for (int i = 0; i < 4; i++) {
            int idx4 = tid + i * 256;
            int m  = idx4 >> 3;
            int c4 = idx4 & 7;
            float4 v = *(const float4*)(x + (size_t)(m0 + m) * CC + k0 + c4 * 4);
            Xs[m][c4 * 4 + 0] = to_tf32(v.x);
            Xs[m][c4 * 4 + 1] = to_tf32(v.y);
            Xs[m][c4 * 4 + 2] = to_tf32(v.z);
            Xs[m][c4 * 4 + 3] = to_tf32(v.w);
        }
        #pragma unroll
        for (int i = 0; i < 2; i++) {
            int idx4 = tid + i * 256;
            int k  = idx4 >> 4;
            int n4 = idx4 & 15;
            float4 v = *(const float4*)(W + (size_t)(k0 + k) * HH + n4 * 4);
            Ws[k][n4 * 4 + 0] = to_tf32(v.x);
            Ws[k][n4 * 4 + 1] = to_tf32(v.y);
            Ws[k][n4 * 4 + 2] = to_tf32(v.z);
            Ws[k][n4 * 4 + 3] = to_tf32(v.w);
        }
        __syncthreads();

        #pragma unroll
        for (int ks = 0; ks < 4; ks++) {
            const int kk = ks * 8;
            uint32_t a[2][4], bfr[4][2];
            #pragma unroll
            for (int mt = 0; mt < 2; mt++) {
                int r = wm * 32 + mt * 16 + g;
                int c = kk + t;
                a[mt][0] = Xs32[(r)     * 36 + c];
                a[mt][1] = Xs32[(r + 8) * 36 + c];
                a[mt][2] = Xs32[(r)     * 36 + c + 4];
                a[mt][3] = Xs32[(r + 8) * 36 + c + 4];
            }
            #pragma unroll
            for (int nt = 0; nt < 4; nt++) {
                int n = wn * 32 + nt * 8 + g;
                bfr[nt][0] = Ws32[(kk + t)     * 68 + n];
                bfr[nt][1] = Ws32[(kk + t + 4) * 68 + n];
            }
            #pragma unroll
            for (int mt = 0; mt < 2; mt++)
                #pragma unroll
                for (int nt = 0; nt < 4; nt++)
                    mma_tf32(acc[mt][nt], a[mt], bfr[nt]);
        }
        __syncthreads();
    }

    #pragma unroll
    for (int mt = 0; mt < 2; mt++) {
        int r0 = m0 + wm * 32 + mt * 16 + g;
        #pragma unroll
        for (int nt = 0; nt < 4; nt++) {
            int cb = wn * 32 + nt * 8 + 2 * t;
            float2 lo = make_float2(acc[mt][nt][0], acc[mt][nt][1]);
            float2 hi = make_float2(acc[mt][nt][2], acc[mt][nt][3]);
            *(float2*)(Out + (size_t)(r0)     * HH + cb) = lo;
            *(float2*)(Out + (size_t)(r0 + 8) * HH + cb) = hi;
        }
    }
}

// ---------------------------------------------------------------------------
// Flash attention on tensor cores (TF32 mma, fp32 accum).
// Block: 64 q-rows x one batch, 128 threads (4 warps, 16 q-rows each).
// KV tile = 64. Q A-fragments live in registers for the whole kernel.
// smem: Vs[64][72]; union{ Kt[64][72] (GEMM1) / Ps[64][76] (P for GEMM2) }.
// Strides: 72 = 8 mod 32 -> conflict-free B-frag reads; 76 = 12 mod 32 ->
// conflict-free A-frag reads. Total smem 37.9KB (< 48KB static).
// ---------------------------------------------------------------------------
#define KSTR 72
#define PSTR 76

__global__ __launch_bounds__(128)
void attn3(float* __restrict__ out) {
    const int b    = blockIdx.y;
    const int qb   = blockIdx.x;
    const int q0   = qb * 64;
    const int tid  = threadIdx.x;
    const int lane = tid & 31;
    const int warp = tid >> 5;          // 0..3 : q rows warp*16..+15
    const int g    = lane >> 2;         // 0..7
    const int t    = lane & 3;          // 0..3

    __shared__ __align__(16) float sKP[64 * PSTR];  // Kt (stride 72) / Ps (stride 76)
    __shared__ __align__(16) float sV[64 * KSTR];

    float*    Kt   = sKP;
    float*    Ps   = sKP;
    uint32_t* Kt32 = (uint32_t*)sKP;
    uint32_t* Ps32 = (uint32_t*)sKP;
    uint32_t* Vs32 = (uint32_t*)sV;

    const int r0 = warp * 16 + g;       // this thread's upper q-row (block-local)

    // ---- Stage Q (scaled, tf32) into Ps region, extract A-fragments --------
    {
        int q  = tid >> 1;
        int h0 = (tid & 1) * 32;
        const float4* src = (const float4*)(g_Q + (size_t)(b * TT + q0 + q) * HH + h0);
        float* dst = Ps + q * PSTR + h0;
        #pragma unroll
        for (int j = 0; j < 8; j++) {
            float4 v = src[j];
            float4 w;
            w.x = to_tf32(v.x * 0.125f);
            w.y = to_tf32(v.y * 0.125f);
            w.z = to_tf32(v.z * 0.125f);
            w.w = to_tf32(v.w * 0.125f);
            *(float4*)(dst + j * 4) = w;
        }
    }
    __syncwarp();                       // staging rows are warp-local

    uint32_t qa[8][4];
    #pragma unroll
    for (int ks = 0; ks < 8; ks++) {
        int c = ks * 8 + t;
        qa[ks][0] = Ps32[(r0)     * PSTR + c];
        qa[ks][1] = Ps32[(r0 + 8) * PSTR + c];
        qa[ks][2] = Ps32[(r0)     * PSTR + c + 4];
        qa[ks][3] = Ps32[(r0 + 8) * PSTR + c + 4];
    }

    float o[8][4];
    #pragma unroll
    for (int nt = 0; nt < 8; nt++)
        #pragma unroll
        for (int r = 0; r < 4; r++) o[nt][r] = 0.f;
    float mr0 = -1e30f, mr1 = -1e30f, l0 = 0.f, l1 = 0.f;

    const int ntiles = qb + 1;
    for (int jt = 0; jt < ntiles; jt++) {
        const int k0 = jt * 64;

        __syncthreads();   // prev tile's GEMM2 done with Vs; Q frags extracted
        // Load K transposed (tf32): Kt[h][k]
        {
            int k  = tid >> 1;
            int h0 = (tid & 1) * 32;
            const float4* src = (const float4*)(g_K + (size_t)(b * TT + k0 + k) * HH + h0);
            #pragma unroll
            for (int j = 0; j < 8; j++) {
                float4 v = src[j];
                Kt[(h0 + j * 4 + 0) * KSTR + k] = to_tf32(v.x);
                Kt[(h0 + j * 4 + 1) * KSTR + k] = to_tf32(v.y);
                Kt[(h0 + j * 4 + 2) * KSTR + k] = to_tf32(v.z);
                Kt[(h0 + j * 4 + 3) * KSTR + k] = to_tf32(v.w);
            }
        }
        // Load V natural (tf32): Vs[k][h]
        {
            int k  = tid >> 1;
            int h0 = (tid & 1) * 32;
            const float4* src = (const float4*)(g_V + (size_t)(b * TT + k0 + k) * HH + h0);
            float* dst = sV + k * KSTR + h0;
            #pragma unroll
            for (int j = 0; j < 8; j++) {
                float4 v = src[j];
                float4 w;
                w.x = to_tf32(v.x); w.y = to_tf32(v.y);
                w.z = to_tf32(v.z); w.w = to_tf32(v.w);
                *(float4*)(dst + j * 4) = w;
            }
        }
        __syncthreads();

        // ---- GEMM1: S[16x64 per warp] = Qsc @ K^T --------------------------
        float s[8][4];
        #pragma unroll
        for (int nt = 0; nt < 8; nt++)
            #pragma unroll
            for (int r = 0; r < 4; r++) s[nt][r] = 0.f;

        #pragma unroll
        for (int ks = 0; ks < 8; ks++) {
            const int kr = ks * 8;
            #pragma unroll
            for (int nt = 0; nt < 8; nt++) {
                uint32_t bf[2];
                bf[0] = Kt32[(kr + t)     * KSTR + nt * 8 + g];
                bf[1] = Kt32[(kr + t + 4) * KSTR + nt * 8 + g];
                mma_tf32(s[nt], qa[ks], bf);
            }
        }

        // ---- Causal mask (diagonal tile only) ------------------------------
        if (jt == qb) {
            #pragma unroll
            for (int nt = 0; nt < 8; nt++) {
                int kc = nt * 8 + 2 * t;
                if (kc     > r0)     s[nt][0] = -1e30f;
                if (kc + 1 > r0)     s[nt][1] = -1e30f;
                if (kc     > r0 + 8) s[nt][2] = -1e30f;
                if (kc + 1 > r0 + 8) s[nt][3] = -1e30f;
            }
        }

        // ---- Online softmax (registers, quad-shfl row reductions) ----------
        float mx0 = -1e30f, mx1 = -1e30f;
        #pragma unroll
        for (int nt = 0; nt < 8; nt++) {
            mx0 = fmaxf(mx0, fmaxf(s[nt][0], s[nt][1]));
            mx1 = fmaxf(mx1, fmaxf(s[nt][2], s[nt][3]));
        }
        mx0 = fmaxf(mx0, __shfl_xor_sync(0xffffffffu, mx0, 1));
        mx0 = fmaxf(mx0, __shfl_xor_sync(0xffffffffu, mx0, 2));
        mx1 = fmaxf(mx1, __shfl_xor_sync(0xffffffffu, mx1, 1));
        mx1 = fmaxf(mx1, __shfl_xor_sync(0xffffffffu, mx1, 2));

        float nm0 = fmaxf(mr0, mx0), nm1 = fmaxf(mr1, mx1);
        float a0 = __expf(mr0 - nm0), a1 = __expf(mr1 - nm1);
        mr0 = nm0; mr1 = nm1;

        float ls0 = 0.f, ls1 = 0.f;
        #pragma unroll
        for (int nt = 0; nt < 8; nt++) {
            s[nt][0] = __expf(s[nt][0] - nm0);
            s[nt][1] = __expf(s[nt][1] - nm0);
            s[nt][2] = __expf(s[nt][2] - nm1);
            s[nt][3] = __expf(s[nt][3] - nm1);
            ls0 += s[nt][0] + s[nt][1];
            ls1 += s[nt][2] + s[nt][3];
        }
        ls0 += __shfl_xor_sync(0xffffffffu, ls0, 1);
        ls0 += __shfl_xor_sync(0xffffffffu, ls0, 2);
        ls1 += __shfl_xor_sync(0xffffffffu, ls1, 1);
        ls1 += __shfl_xor_sync(0xffffffffu, ls1, 2);
        l0 = l0 * a0 + ls0;
        l1 = l1 * a1 + ls1;
        #pragma unroll
        for (int nt = 0; nt < 8; nt++) {
            o[nt][0] *= a0; o[nt][1] *= a0;
            o[nt][2] *= a1; o[nt][3] *= a1;
        }

        __syncthreads();   // all warps done reading Kt before P overlays it

        // ---- Store P (tf32) into Ps[q][k] ---------------------------------
        #pragma unroll
        for (int nt = 0; nt < 8; nt++) {
            int kc = nt * 8 + 2 * t;
            float2 p0 = make_float2(to_tf32(s[nt][0]), to_tf32(s[nt][1]));
            float2 p1 = make_float2(to_tf32(s[nt][2]), to_tf32(s[nt][3]));
            *(float2*)(Ps + (r0)     * PSTR + kc) = p0;
            *(float2*)(Ps + (r0 + 8) * PSTR + kc) = p1;
        }
        __syncwarp();      // P rows are warp-local: warp-level visibility suffices

        // ---- GEMM2: O[16x64 per warp] += P @ V -----------------------------
        #pragma unroll
        for (int ks = 0; ks < 8; ks++) {
            const int kr = ks * 8;
            uint32_t pa[4];
            pa[0] = Ps32[(r0)     * PSTR + kr + t];
            pa[1] = Ps32[(r0 + 8) * PSTR + kr + t];
            pa[2] = Ps32[(r0)     * PSTR + kr + t + 4];
            pa[3] = Ps32[(r0 + 8) * PSTR + kr + t + 4];
            #pragma unroll
            for (int nt = 0; nt < 8; nt++) {
                uint32_t bf[2];
                bf[0] = Vs32[(kr + t)     * KSTR + nt * 8 + g];
                bf[1] = Vs32[(kr + t + 4) * KSTR + nt * 8 + g];
                mma_tf32(o[nt], pa, bf);
            }
        }
    }

    // ---- Normalize + store --------------------------------------------------
    const float inv0 = 1.f / l0;
    const float inv1 = 1.f / l1;
    #pragma unroll
    for (int nt = 0; nt < 8; nt++) {
        int cb = nt * 8 + 2 * t;
        float2 lo = make_float2(o[nt][0] * inv0, o[nt][1] * inv0);
        float2 hi = make_float2(o[nt][2] * inv1, o[nt][3] * inv1);
        *(float2*)(out + (size_t)(b * TT + q0 + r0)     * HH + cb) = lo;
        *(float2*)(out + (size_t)(b * TT + q0 + r0 + 8) * HH + cb) = hi;
    }
}

// ---------------------------------------------------------------------------
extern "C" void kernel_launch(void* const* d_in, const int* in_sizes, int n_in,
                              void* d_out, int out_size) {
    const float* x  = (const float*)d_in[0];
    const float* Wq = (const float*)d_in[1];
    const float* Wk = (const float*)d_in[2];
    const float* Wv = (const float*)d_in[3];
    float* out = (float*)d_out;

    proj_mma<<<dim3(BT / 128, 3), 256>>>(x, Wq, Wk, Wv);
    attn3<<<dim3(TT / 64, BB), 128>>>(out);
}